// round 14
// baseline (speedup 1.0000x reference)
#include <cuda_runtime.h>
#include <cuda_bf16.h>
#include <math.h>
#include <stdint.h>

#define SEQ    2048
#define DMODEL 2048
#define NH     32
#define NKVH   8
#define HD     64
#define QDIM   2048
#define KVDIM  512

#define KC          32
#define B_TILE_B    10240                 // 128 rows * 80 B

#define GEMM_SMEM_MT2   81920             // 2 stages * (2*10240 + 2*10240)
#define GEMM_SMEM_MT4   184320            // 3 stages * (2*20480 + 2*10240)

#define ATT_STRIDE  144
#define ATT_COMP    9216
#define ATT_STAGE   (4 * ATT_COMP)
#define ATT_SMEM    (2 * ATT_STAGE)       // 73728

#define PREP_PRE_BLOCKS   16640
#define PREP_QKV_BLOCKS   6144
#define PREP_WO_BLOCKS    4096
#define PREP_BLOCKS       (PREP_PRE_BLOCKS + PREP_QKV_BLOCKS + PREP_WO_BLOCKS)

// ---------------- scratch ----------------
__device__ __align__(128) float g_cos[SEQ * 32];
__device__ __align__(128) float g_sin[SEQ * 32];

__device__ __align__(128) __nv_bfloat16 g_xhi[SEQ * DMODEL];
__device__ __align__(128) __nv_bfloat16 g_xlo[SEQ * DMODEL];
__device__ __align__(128) __nv_bfloat16 g_wqh[QDIM * DMODEL];
__device__ __align__(128) __nv_bfloat16 g_wql[QDIM * DMODEL];
__device__ __align__(128) __nv_bfloat16 g_wkh[KVDIM * DMODEL];
__device__ __align__(128) __nv_bfloat16 g_wkl[KVDIM * DMODEL];
__device__ __align__(128) __nv_bfloat16 g_wvh[KVDIM * DMODEL];
__device__ __align__(128) __nv_bfloat16 g_wvl[KVDIM * DMODEL];
__device__ __align__(128) __nv_bfloat16 g_woh[DMODEL * QDIM];
__device__ __align__(128) __nv_bfloat16 g_wol[DMODEL * QDIM];
__device__ __align__(128) __nv_bfloat16 g_ahi[SEQ * QDIM];
__device__ __align__(128) __nv_bfloat16 g_alo[SEQ * QDIM];
__device__ __align__(128) __nv_bfloat16 g_qh[NH * SEQ * HD];
__device__ __align__(128) __nv_bfloat16 g_ql[NH * SEQ * HD];
__device__ __align__(128) __nv_bfloat16 g_kh[NKVH * SEQ * HD];
__device__ __align__(128) __nv_bfloat16 g_kl[NKVH * SEQ * HD];
__device__ __align__(128) __nv_bfloat16 g_vh[NKVH * SEQ * HD];
__device__ __align__(128) __nv_bfloat16 g_vl[NKVH * SEQ * HD];

// ---------------- helpers ----------------
__device__ __forceinline__ uint32_t smem_u32(const void* p) {
    uint32_t a;
    asm("{ .reg .u64 t; cvta.to.shared.u64 t, %1; cvt.u32.u64 %0, t; }" : "=r"(a) : "l"(p));
    return a;
}
__device__ __forceinline__ void ldsm4(uint32_t* r, uint32_t addr) {
    asm volatile("ldmatrix.sync.aligned.m8n8.x4.shared.b16 {%0,%1,%2,%3}, [%4];"
        : "=r"(r[0]), "=r"(r[1]), "=r"(r[2]), "=r"(r[3]) : "r"(addr));
}
__device__ __forceinline__ void ldsm4t(uint32_t* r, uint32_t addr) {
    asm volatile("ldmatrix.sync.aligned.m8n8.x4.trans.shared.b16 {%0,%1,%2,%3}, [%4];"
        : "=r"(r[0]), "=r"(r[1]), "=r"(r[2]), "=r"(r[3]) : "r"(addr));
}
__device__ __forceinline__ void mma_bf16(float* c, const uint32_t* a, const uint32_t* b) {
    asm("mma.sync.aligned.m16n8k16.row.col.f32.bf16.bf16.f32 "
        "{%0,%1,%2,%3}, {%4,%5,%6,%7}, {%8,%9}, {%0,%1,%2,%3};"
        : "+f"(c[0]), "+f"(c[1]), "+f"(c[2]), "+f"(c[3])
        : "r"(a[0]), "r"(a[1]), "r"(a[2]), "r"(a[3]), "r"(b[0]), "r"(b[1]));
}
__device__ __forceinline__ void cp16(uint32_t saddr, const void* gptr) {
    asm volatile("cp.async.cg.shared.global [%0], [%1], 16;" :: "r"(saddr), "l"(gptr));
}
__device__ __forceinline__ uint32_t pack_split(float x, float y, uint32_t* lo) {
    __nv_bfloat162 hb = __floats2bfloat162_rn(x, y);
    float rx = x - __bfloat162float(hb.x);
    float ry = y - __bfloat162float(hb.y);
    __nv_bfloat162 lb = __floats2bfloat162_rn(rx, ry);
    *lo = *reinterpret_cast<uint32_t*>(&lb);
    return *reinterpret_cast<uint32_t*>(&hb);
}

// ---------------- weight transpose + split ----------------
__device__ __forceinline__ void conv_wt_body(const float* __restrict__ W,
                                             __nv_bfloat16* __restrict__ hi,
                                             __nv_bfloat16* __restrict__ lo,
                                             int Krows, int N, int bxb, int byb,
                                             int x, int y) {
    __shared__ float t[32][33];
    int bx = bxb * 32, by = byb * 32;
#pragma unroll
    for (int r = 0; r < 32; r += 8)
        t[y + r][x] = W[(size_t)(by + y + r) * N + bx + x];
    __syncthreads();
#pragma unroll
    for (int r = 0; r < 32; r += 8) {
        float v = t[x][y + r];
        __nv_bfloat16 h = __float2bfloat16(v);
        size_t o = (size_t)(bx + y + r) * Krows + by + x;
        hi[o] = h;
        lo[o] = __float2bfloat16(v - __bfloat162float(h));
    }
}

// ---------------- launch 1: ALL prep ----------------
__global__ void prep_kernel(const float* __restrict__ x,
                            const float* __restrict__ Wq,
                            const float* __restrict__ Wk,
                            const float* __restrict__ Wv,
                            const float* __restrict__ Wo) {
    int b = blockIdx.x;
    int tid = threadIdx.x;
    if (b < PREP_PRE_BLOCKS) {
        int idx = b * 256 + tid;
        if (idx < SEQ * 32) {
            int s = idx >> 5, d2 = idx & 31;
            double inv = exp(-(double)d2 * 0.28782313662425572);
            double f = (double)s * inv;
            g_cos[idx] = (float)cos(f);
            g_sin[idx] = (float)sin(f);
        }
        int xi = idx - SEQ * 32;
        if (xi >= 0 && xi < SEQ * DMODEL) {
            float v = x[xi];
            __nv_bfloat16 h = __float2bfloat16(v);
            g_xhi[xi] = h;
            g_xlo[xi] = __float2bfloat16(v - __bfloat162float(h));
        }
        return;
    }
    int tx = tid & 31, ty = tid >> 5;
    if (b < PREP_PRE_BLOCKS + PREP_QKV_BLOCKS) {
        int i = b - PREP_PRE_BLOCKS;
        int bx = i % 96, by = i / 96;
        if (bx < 64)      conv_wt_body(Wq, g_wqh, g_wql, DMODEL, QDIM,  bx,      by, tx, ty);
        else if (bx < 80) conv_wt_body(Wk, g_wkh, g_wkl, DMODEL, KVDIM, bx - 64, by, tx, ty);
        else              conv_wt_body(Wv, g_wvh, g_wvl, DMODEL, KVDIM, bx - 80, by, tx, ty);
    } else {
        int i = b - PREP_PRE_BLOCKS - PREP_QKV_BLOCKS;
        conv_wt_body(Wo, g_woh, g_wol, QDIM, DMODEL, i % 64, i / 64, tx, ty);
    }
}

// ---------------- mma.sync GEMM core, templated on M-tile + stages ----------------
// MT = number of 64-row M blocks (2 -> 128x128/256thr, 4 -> 256x128/512thr)
// NST = pipeline stages (2 or 3)
template<int MT, int NST>
__device__ __forceinline__ void gemm_core(
    const __nv_bfloat16* __restrict__ Ahi, const __nv_bfloat16* __restrict__ Alo,
    const __nv_bfloat16* __restrict__ Bhi, const __nv_bfloat16* __restrict__ Blo,
    int K, int m0, int n0, char* smem,
    int mode, float* __restrict__ C, int ldc,
    __nv_bfloat16* __restrict__ dhi, __nv_bfloat16* __restrict__ dlo)
{
    constexpr int A_TILE = MT * 64 * 80;
    constexpr int OFF_AL = A_TILE;
    constexpr int OFF_BH = 2 * A_TILE;
    constexpr int STAGE  = 2 * A_TILE + 2 * B_TILE_B;
    constexpr int RSTRIDE = MT * 32;
    constexpr int BREPS = 4 / MT;

    int tid = threadIdx.x, lane = tid & 31, wid = tid >> 5;
    int wm = wid >> 2, wn = wid & 3;
    uint32_t sb = smem_u32(smem);

    const __nv_bfloat16* srcA[2] = { Ahi + (size_t)m0 * K, Alo + (size_t)m0 * K };
    const __nv_bfloat16* srcB[2] = { Bhi + (size_t)n0 * K, Blo + (size_t)n0 * K };

    float acc[4][4][4];
#pragma unroll
    for (int a = 0; a < 4; a++)
#pragma unroll
        for (int b = 0; b < 4; b++)
#pragma unroll
            for (int c = 0; c < 4; c++) acc[a][b][c] = 0.f;

    const int nchunks = K / KC;
    int row0 = tid >> 2, seg = tid & 3;

    // prologue: issue chunks 0 .. NST-2
#pragma unroll
    for (int c = 0; c < NST - 1; c++) {
        uint32_t st = sb + c * STAGE;
        int k0 = c * KC;
#pragma unroll
        for (int comp = 0; comp < 2; comp++) {
#pragma unroll
            for (int it = 0; it < 2; it++) {
                int r = row0 + it * RSTRIDE;
                cp16(st + comp * A_TILE + r * 80 + seg * 16,
                     srcA[comp] + (size_t)r * K + k0 + seg * 8);
            }
#pragma unroll
            for (int ib = 0; ib < BREPS; ib++) {
                int r = row0 + ib * RSTRIDE;
                cp16(st + OFF_BH + comp * B_TILE_B + r * 80 + seg * 16,
                     srcB[comp] + (size_t)r * K + k0 + seg * 8);
            }
        }
        asm volatile("cp.async.commit_group;");
    }

    for (int i = 0; i < nchunks; i++) {
        // chunk i must be complete; with 3 stages allow one group in flight
        if (NST == 3 && i + 1 < nchunks) {
            asm volatile("cp.async.wait_group 1;");
        } else {
            asm volatile("cp.async.wait_group 0;");
        }
        __syncthreads();

        int pfc = i + NST - 1;     // chunk to prefetch
        if (pfc < nchunks) {
            uint32_t st = sb + (pfc % NST) * STAGE;
            int k0 = pfc * KC;
#pragma unroll
            for (int comp = 0; comp < 2; comp++) {
#pragma unroll
                for (int it = 0; it < 2; it++) {
                    int r = row0 + it * RSTRIDE;
                    cp16(st + comp * A_TILE + r * 80 + seg * 16,
                         srcA[comp] + (size_t)r * K + k0 + seg * 8);
                }
#pragma unroll
                for (int ib = 0; ib < BREPS; ib++) {
                    int r = row0 + ib * RSTRIDE;
                    cp16(st + OFF_BH + comp * B_TILE_B + r * 80 + seg * 16,
                         srcB[comp] + (size_t)r * K + k0 + seg * 8);
                }
            }
            asm volatile("cp.async.commit_group;");
        }

        uint32_t st = sb + (i % NST) * STAGE;
#pragma unroll
        for (int ks = 0; ks < 2; ks++) {
            uint32_t bh[4][2], bl[4][2];
            uint32_t brow = wn * 32 + ((lane >> 4) & 1) * 8 + (lane & 7);
            uint32_t bcol = ks * 16 + ((lane >> 3) & 1) * 8;
#pragma unroll
            for (int pr = 0; pr < 2; pr++) {
                uint32_t bd = st + OFF_BH + (brow + pr * 16) * 80 + bcol * 2;
                uint32_t t4[4];
                ldsm4(t4, bd);
                bh[2 * pr][0] = t4[0]; bh[2 * pr][1] = t4[1];
                bh[2 * pr + 1][0] = t4[2]; bh[2 * pr + 1][1] = t4[3];
                ldsm4(t4, bd + B_TILE_B);
                bl[2 * pr][0] = t4[0]; bl[2 * pr][1] = t4[1];
                bl[2 * pr + 1][0] = t4[2]; bl[2 * pr + 1][1] = t4[3];
            }
            uint32_t arow = wm * 64 + (lane & 15);
            uint32_t acol = ks * 16 + (lane >> 4) * 8;
#pragma unroll
            for (int mi = 0; mi < 4; mi++) {
                uint32_t ah[4], al[4];
                uint32_t ad = st + (arow + mi * 16) * 80 + acol * 2;
                ldsm4(ah, ad);
                ldsm4(al, ad + OFF_AL);
#pragma unroll
                for (int ni = 0; ni < 4; ni++) {
                    mma_bf16(acc[mi][ni], ah, bh[ni]);
                    mma_bf16(acc[mi][ni], ah, bl[ni]);
                    mma_bf16(acc[mi][ni], al, bh[ni]);
                }
            }
        }
    }

    int r4 = lane >> 2, c2 = (lane & 3) * 2;
    if (mode == 0) {
        float* Cw = C + (size_t)(m0 + wm * 64) * ldc + n0 + wn * 32;
#pragma unroll
        for (int mi = 0; mi < 4; mi++)
#pragma unroll
            for (int ni = 0; ni < 4; ni++) {
                float* p = Cw + (size_t)(mi * 16 + r4) * ldc + ni * 8 + c2;
                *(float2*)p = make_float2(acc[mi][ni][0], acc[mi][ni][1]);
                *(float2*)(p + (size_t)8 * ldc) = make_float2(acc[mi][ni][2], acc[mi][ni][3]);
            }
    } else {
        float qsc = (mode == 1) ? 0.18033688011112042f : 1.0f;
#pragma unroll
        for (int mi = 0; mi < 4; mi++)
#pragma unroll
            for (int ni = 0; ni < 4; ni++) {
                int col = n0 + wn * 32 + ni * 8 + c2;
                int h = col >> 6, d2 = (col & 63) >> 1;
#pragma unroll
                for (int half = 0; half < 2; half++) {
                    int s = m0 + wm * 64 + mi * 16 + r4 + half * 8;
                    float v0 = acc[mi][ni][half * 2];
                    float v1 = acc[mi][ni][half * 2 + 1];
                    float o0, o1;
                    if (mode == 3) { o0 = v0; o1 = v1; }
                    else {
                        float c = g_cos[s * 32 + d2], sn = g_sin[s * 32 + d2];
                        o0 = (v0 * c - v1 * sn) * qsc;
                        o1 = (v0 * sn + v1 * c) * qsc;
                    }
                    size_t off = ((size_t)h * SEQ + s) * HD + 2 * d2;
                    uint32_t lo, hi = pack_split(o0, o1, &lo);
                    *(uint32_t*)(dhi + off) = hi;
                    *(uint32_t*)(dlo + off) = lo;
                }
            }
    }
}

// launch 2: fused QKV GEMM + RoPE (128x128, 256 thr, 2 CTA/SM, 2-stage)
__global__ void __launch_bounds__(256, 2) qkv_gemm_kernel() {
    extern __shared__ char smem[];
    int bn = blockIdx.x, bm = blockIdx.y;
    if (bn < 16)
        gemm_core<2, 2>(g_xhi, g_xlo, g_wqh, g_wql, DMODEL, bm * 128, bn * 128, smem,
                        1, nullptr, 0, g_qh, g_ql);
    else if (bn < 20)
        gemm_core<2, 2>(g_xhi, g_xlo, g_wkh, g_wkl, DMODEL, bm * 128, (bn - 16) * 128, smem,
                        2, nullptr, 0, g_kh, g_kl);
    else
        gemm_core<2, 2>(g_xhi, g_xlo, g_wvh, g_wvl, DMODEL, bm * 128, (bn - 20) * 128, smem,
                        3, nullptr, 0, g_vh, g_vl);
}

// launch 4: output projection (256x128, 512 thr, 128 CTAs, 3-stage pipeline)
__global__ void __launch_bounds__(512, 1) out_gemm_kernel(float* __restrict__ out) {
    extern __shared__ char smem[];
    gemm_core<4, 3>(g_ahi, g_alo, g_woh, g_wol, QDIM,
                    blockIdx.y * 256, blockIdx.x * 128, smem,
                    0, out, DMODEL, nullptr, nullptr);
}

// ---------------- launch 3: tensor-core flash attention ----------------
// l-reduction deferred to epilogue (per-thread partials; rescale is linear).
__global__ __launch_bounds__(128) void attn_mma_kernel() {
    extern __shared__ char smc[];
    uint32_t sb = smem_u32(smc);
    int tid = threadIdx.x, lane = tid & 31, w = tid >> 5;
    int qb = (int)gridDim.x - 1 - (int)blockIdx.x;
    int h = blockIdx.y, kvh = h >> 2;

    const __nv_bfloat16* qh_g = g_qh + ((size_t)h * SEQ + qb * 64) * HD;
    const __nv_bfloat16* ql_g = g_ql + ((size_t)h * SEQ + qb * 64) * HD;
    const __nv_bfloat16* kv_g[4] = {
        g_kh + (size_t)kvh * SEQ * HD, g_kl + (size_t)kvh * SEQ * HD,
        g_vh + (size_t)kvh * SEQ * HD, g_vl + (size_t)kvh * SEQ * HD };

#pragma unroll
    for (int i = 0; i < 8; i++) {
        int c = tid + i * 128;
        int comp = c >> 9, idx = c & 511, row = idx >> 3, seg = idx & 7;
        const __nv_bfloat16* s = (comp ? ql_g : qh_g) + row * HD + seg * 8;
        cp16(sb + comp * ATT_COMP + row * ATT_STRIDE + seg * 16, s);
    }
    {
        uint32_t base = sb + ATT_STAGE;
#pragma unroll
        for (int i = 0; i < 16; i++) {
            int c = tid + i * 128;
            int comp = c >> 9, idx = c & 511, row = idx >> 3, seg = idx & 7;
            cp16(base + comp * ATT_COMP + row * ATT_STRIDE + seg * 16,
                 kv_g[comp] + (size_t)row * HD + seg * 8);
        }
    }
    asm volatile("cp.async.commit_group;");

    float m0 = -1e30f, m1 = -1e30f, l0 = 0.f, l1 = 0.f;
    float oacc[8][4];
#pragma unroll
    for (int j = 0; j < 8; j++)
#pragma unroll
        for (int e = 0; e < 4; e++) oacc[j][e] = 0.f;

    uint32_t qfh[4][4], qfl[4][4];

    for (int kb = 0; kb <= qb; kb++) {
        asm volatile("cp.async.wait_group 0;");
        __syncthreads();

        if (kb == 0) {
#pragma unroll
            for (int ks = 0; ks < 4; ks++) {
                uint32_t ad = sb + (w * 16 + (lane & 15)) * ATT_STRIDE
                            + (ks * 16 + ((lane >> 4) << 3)) * 2;
                ldsm4(qfh[ks], ad);
                ldsm4(qfl[ks], ad + ATT_COMP);
            }
            __syncthreads();
        }

        if (kb < qb) {
            uint32_t base = sb + (kb & 1) * ATT_STAGE;
#pragma unroll
            for (int i = 0; i < 16; i++) {
                int c = tid + i * 128;
                int comp = c >> 9, idx = c & 511, row = idx >> 3, seg = idx & 7;
                cp16(base + comp * ATT_COMP + row * ATT_STRIDE + seg * 16,
                     kv_g[comp] + (size_t)((kb + 1) * 64 + row) * HD + seg * 8);
            }
            asm volatile("cp.async.commit_group;");
        }

        uint32_t stg = sb + ((kb + 1) & 1) * ATT_STAGE;

        float sacc[8][4];
#pragma unroll
        for (int j = 0; j < 8; j++)
#pragma unroll
            for (int e = 0; e < 4; e++) sacc[j][e] = 0.f;

#pragma unroll
        for (int ks = 0; ks < 4; ks++) {
#pragma unroll
            for (int jp = 0; jp < 4; jp++) {
                uint32_t r = jp * 16 + ((lane >> 3) & 1) * 8 + (lane & 7);
                uint32_t ad = stg + r * ATT_STRIDE + (ks * 16 + (lane >> 4) * 8) * 2;
                uint32_t bh[4], bl[4];
                ldsm4(bh, ad);
                ldsm4(bl, ad + ATT_COMP);
                uint32_t b0h[2] = {bh[0], bh[2]}, b1h[2] = {bh[1], bh[3]};
                uint32_t b0l[2] = {bl[0], bl[2]}, b1l[2] = {bl[1], bl[3]};
                mma_bf16(sacc[2 * jp],     qfh[ks], b0h);
                mma_bf16(sacc[2 * jp],     qfh[ks], b0l);
                mma_bf16(sacc[2 * jp],     qfl[ks], b0h);
                mma_bf16(sacc[2 * jp + 1], qfh[ks], b1h);
                mma_bf16(sacc[2 * jp + 1], qfh[ks], b1l);
                mma_bf16(sacc[2 * jp + 1], qfl[ks], b1h);
            }
        }

        if (kb == qb) {
            int rb = w * 16 + (lane >> 2), cb = (lane & 3) * 2;
#pragma unroll
            for (int j = 0; j < 8; j++)
#pragma unroll
                for (int e = 0; e < 4; e++) {
                    int col = j * 8 + cb + (e & 1);
                    int rowi = rb + ((e & 2) ? 8 : 0);
                    if (col > rowi) sacc[j][e] = -1e30f;
                }
        }

        float mx0 = -1e30f, mx1 = -1e30f;
#pragma unroll
        for (int j = 0; j < 8; j++) {
            mx0 = fmaxf(mx0, fmaxf(sacc[j][0], sacc[j][1]));
            mx1 = fmaxf(mx1, fmaxf(sacc[j][2], sacc[j][3]));
        }
        mx0 = fmaxf(mx0, __shfl_xor_sync(0xffffffffu, mx0, 1));
        mx0 = fmaxf(mx0, __shfl_xor_sync(0xffffffffu, mx0, 2));
        mx1 = fmaxf(mx1, __shfl_xor_sync(0xffffffffu, mx1, 1));
        mx1 = fmaxf(mx1, __shfl_xor_sync(0xffffffffu, mx1, 2));
        float nm0 = fmaxf(m0, mx0), nm1 = fmaxf(m1, mx1);

        bool noup = __all_sync(0xffffffffu, (nm0 == m0) && (nm1 == m1));
        if (!noup) {
            float cr0 = exp2f(m0 - nm0), cr1 = exp2f(m1 - nm1);
            l0 *= cr0; l1 *= cr1;    // per-thread partials; rescale is linear
#pragma unroll
            for (int j = 0; j < 8; j++) {
                oacc[j][0] *= cr0; oacc[j][1] *= cr0;
                oacc[j][2] *= cr1; oacc[j][3] *= cr1;
            }
            m0 = nm0; m1 = nm1;
        }

        uint32_t pah[4][4], pal[4][4];
#pragma unroll
        for (int ks = 0; ks < 4; ks++) {
            int j0 = 2 * ks, j1 = 2 * ks + 1;
            float p00 = exp2f(sacc[j0][0] - m0), p01 = exp2f(sacc[j0][1] - m0);
            float p02 = exp2f(sacc[j0][2] - m1), p03 = exp2f(sacc[j0][3] - m1);
            float p10 = exp2f(sacc[j1][0] - m0), p11 = exp2f(sacc[j1][1] - m0);
            float p12 = exp2f(sacc[j1][2] - m1), p13 = exp2f(sacc[j1][3] - m1);
            l0 += (p00 + p01) + (p10 + p11);   // defer cross-lane reduction
            l1 += (p02 + p03) + (p12 + p13);
            pah[ks][0] = pack_split(p00, p01, &pal[ks][0]);
            pah[ks][1] = pack_split(p02, p03, &pal[ks][1]);
            pah[ks][2] = pack_split(p10, p11, &pal[ks][2]);
            pah[ks][3] = pack_split(p12, p13, &pal[ks][3]);
        }

#pragma unroll
        for (int ks = 0; ks < 4; ks++) {
#pragma unroll
            for (int jp = 0; jp < 4; jp++) {
                uint32_t r = ks * 16 + ((lane >> 4) << 3) + (lane & 7);
                uint32_t ad = stg + 2 * ATT_COMP + r * ATT_STRIDE
                            + (jp * 16 + ((lane >> 3) & 1) * 8) * 2;
                uint32_t vh[4], vl[4];
                ldsm4t(vh, ad);
                ldsm4t(vl, ad + ATT_COMP);
                uint32_t v0h[2] = {vh[0], vh[2]}, v1h[2] = {vh[1], vh[3]};
                uint32_t v0l[2] = {vl[0], vl[2]}, v1l[2] = {vl[1], vl[3]};
                mma_bf16(oacc[2 * jp],     pah[ks], v0h);
                mma_bf16(oacc[2 * jp],     pah[ks], v0l);
                mma_bf16(oacc[2 * jp],     pal[ks], v0h);
                mma_bf16(oacc[2 * jp + 1], pah[ks], v1h);
                mma_bf16(oacc[2 * jp + 1], pah[ks], v1l);
                mma_bf16(oacc[2 * jp + 1], pal[ks], v1h);
            }
        }
    }

    // final cross-lane l reduction (rows live on 4-lane groups)
    l0 += __shfl_xor_sync(0xffffffffu, l0, 1);
    l0 += __shfl_xor_sync(0xffffffffu, l0, 2);
    l1 += __shfl_xor_sync(0xffffffffu, l1, 1);
    l1 += __shfl_xor_sync(0xffffffffu, l1, 2);

    float i0 = 1.f / l0, i1 = 1.f / l1;
    int r0 = qb * 64 + w * 16 + (lane >> 2);
    size_t colb = (size_t)h * HD + (lane & 3) * 2;
#pragma unroll
    for (int j = 0; j < 8; j++) {
        size_t o0 = (size_t)r0 * QDIM + colb + j * 8;
        size_t o1 = (size_t)(r0 + 8) * QDIM + colb + j * 8;
        uint32_t lo0, hi0 = pack_split(oacc[j][0] * i0, oacc[j][1] * i0, &lo0);
        uint32_t lo1, hi1 = pack_split(oacc[j][2] * i1, oacc[j][3] * i1, &lo1);
        *(uint32_t*)(g_ahi + o0) = hi0;
        *(uint32_t*)(g_alo + o0) = lo0;
        *(uint32_t*)(g_ahi + o1) = hi1;
        *(uint32_t*)(g_alo + o1) = lo1;
    }
}

// ---------------------------------------------------------------------------
extern "C" void kernel_launch(void* const* d_in, const int* in_sizes, int n_in,
                              void* d_out, int out_size) {
    const float* x  = (const float*)d_in[0];
    const float* Wq = (const float*)d_in[1];
    const float* Wk = (const float*)d_in[2];
    const float* Wv = (const float*)d_in[3];
    const float* Wo = (const float*)d_in[4];
    float* out = (float*)d_out;

    cudaFuncSetAttribute(qkv_gemm_kernel,
                         cudaFuncAttributeMaxDynamicSharedMemorySize, GEMM_SMEM_MT2);
    cudaFuncSetAttribute(out_gemm_kernel,
                         cudaFuncAttributeMaxDynamicSharedMemorySize, GEMM_SMEM_MT4);
    cudaFuncSetAttribute(attn_mma_kernel,
                         cudaFuncAttributeMaxDynamicSharedMemorySize, ATT_SMEM);

    prep_kernel<<<PREP_BLOCKS, 256>>>(x, Wq, Wk, Wv, Wo);
    qkv_gemm_kernel<<<dim3(24, 16), 256, GEMM_SMEM_MT2>>>();
    attn_mma_kernel<<<dim3(SEQ / 64, NH), 128, ATT_SMEM>>>();
    out_gemm_kernel<<<dim3(16, 8), 512, GEMM_SMEM_MT4>>>(out);
}

// round 16
// speedup vs baseline: 1.0322x; 1.0322x over previous
#include <cuda_runtime.h>
#include <cuda_bf16.h>
#include <math.h>
#include <stdint.h>

#define SEQ    2048
#define DMODEL 2048
#define NH     32
#define NKVH   8
#define HD     64
#define QDIM   2048
#define KVDIM  512

#define KC          32
#define B_TILE_B    10240                 // 128 rows * 80 B

#define GEMM_SMEM_MT2   81920             // 2 stages * (2*10240 + 2*10240)
#define GEMM_SMEM_MT4   122880            // 2 stages * (2*20480 + 2*10240)

#define ATT_STRIDE  144
#define ATT_COMP    9216
#define ATT_STAGE   (4 * ATT_COMP)
#define ATT_SMEM    (2 * ATT_STAGE)       // 73728

// prep block ranges (256 threads each)
#define PREP_ROPE_BLOCKS  256             // SEQ*32 / 256
#define PREP_X_BLOCKS     4096            // SEQ*DMODEL / (256*4)
#define PREP_QKV_BLOCKS   6144            // 96 * 64
#define PREP_WO_BLOCKS    4096            // 64 * 64
#define PREP_BLOCKS (PREP_ROPE_BLOCKS + PREP_X_BLOCKS + PREP_QKV_BLOCKS + PREP_WO_BLOCKS)

// ---------------- scratch ----------------
__device__ __align__(128) float g_cos[SEQ * 32];
__device__ __align__(128) float g_sin[SEQ * 32];

__device__ __align__(128) __nv_bfloat16 g_xhi[SEQ * DMODEL];
__device__ __align__(128) __nv_bfloat16 g_xlo[SEQ * DMODEL];
__device__ __align__(128) __nv_bfloat16 g_wqh[QDIM * DMODEL];
__device__ __align__(128) __nv_bfloat16 g_wql[QDIM * DMODEL];
__device__ __align__(128) __nv_bfloat16 g_wkh[KVDIM * DMODEL];
__device__ __align__(128) __nv_bfloat16 g_wkl[KVDIM * DMODEL];
__device__ __align__(128) __nv_bfloat16 g_wvh[KVDIM * DMODEL];
__device__ __align__(128) __nv_bfloat16 g_wvl[KVDIM * DMODEL];
__device__ __align__(128) __nv_bfloat16 g_woh[DMODEL * QDIM];
__device__ __align__(128) __nv_bfloat16 g_wol[DMODEL * QDIM];
__device__ __align__(128) __nv_bfloat16 g_ahi[SEQ * QDIM];
__device__ __align__(128) __nv_bfloat16 g_alo[SEQ * QDIM];
__device__ __align__(128) __nv_bfloat16 g_qh[NH * SEQ * HD];
__device__ __align__(128) __nv_bfloat16 g_ql[NH * SEQ * HD];
__device__ __align__(128) __nv_bfloat16 g_kh[NKVH * SEQ * HD];
__device__ __align__(128) __nv_bfloat16 g_kl[NKVH * SEQ * HD];
__device__ __align__(128) __nv_bfloat16 g_vh[NKVH * SEQ * HD];
__device__ __align__(128) __nv_bfloat16 g_vl[NKVH * SEQ * HD];

// ---------------- helpers ----------------
__device__ __forceinline__ uint32_t smem_u32(const void* p) {
    uint32_t a;
    asm("{ .reg .u64 t; cvta.to.shared.u64 t, %1; cvt.u32.u64 %0, t; }" : "=r"(a) : "l"(p));
    return a;
}
__device__ __forceinline__ void ldsm4(uint32_t* r, uint32_t addr) {
    asm volatile("ldmatrix.sync.aligned.m8n8.x4.shared.b16 {%0,%1,%2,%3}, [%4];"
        : "=r"(r[0]), "=r"(r[1]), "=r"(r[2]), "=r"(r[3]) : "r"(addr));
}
__device__ __forceinline__ void ldsm4t(uint32_t* r, uint32_t addr) {
    asm volatile("ldmatrix.sync.aligned.m8n8.x4.trans.shared.b16 {%0,%1,%2,%3}, [%4];"
        : "=r"(r[0]), "=r"(r[1]), "=r"(r[2]), "=r"(r[3]) : "r"(addr));
}
__device__ __forceinline__ void mma_bf16(float* c, const uint32_t* a, const uint32_t* b) {
    asm("mma.sync.aligned.m16n8k16.row.col.f32.bf16.bf16.f32 "
        "{%0,%1,%2,%3}, {%4,%5,%6,%7}, {%8,%9}, {%0,%1,%2,%3};"
        : "+f"(c[0]), "+f"(c[1]), "+f"(c[2]), "+f"(c[3])
        : "r"(a[0]), "r"(a[1]), "r"(a[2]), "r"(a[3]), "r"(b[0]), "r"(b[1]));
}
__device__ __forceinline__ void cp16(uint32_t saddr, const void* gptr) {
    asm volatile("cp.async.cg.shared.global [%0], [%1], 16;" :: "r"(saddr), "l"(gptr));
}
__device__ __forceinline__ uint32_t pack_split(float x, float y, uint32_t* lo) {
    __nv_bfloat162 hb = __floats2bfloat162_rn(x, y);
    float rx = x - __bfloat162float(hb.x);
    float ry = y - __bfloat162float(hb.y);
    __nv_bfloat162 lb = __floats2bfloat162_rn(rx, ry);
    *lo = *reinterpret_cast<uint32_t*>(&lb);
    return *reinterpret_cast<uint32_t*>(&hb);
}

// ---------------- weight transpose + split (4-byte paired stores) ----------------
__device__ __forceinline__ void conv_wt_body(const float* __restrict__ W,
                                             __nv_bfloat16* __restrict__ hi,
                                             __nv_bfloat16* __restrict__ lo,
                                             int Krows, int N, int bxb, int byb,
                                             int tid) {
    __shared__ float t[32][33];
    int bx = bxb * 32, by = byb * 32;
    int x = tid & 31, y = tid >> 5;
#pragma unroll
    for (int r = 0; r < 32; r += 8)
        t[y + r][x] = W[(size_t)(by + y + r) * N + bx + x];
    __syncthreads();
    // phase 2: thread -> (col pair u, row slot rs); 4-byte hi/lo stores
    int u = tid & 15, rs = tid >> 4;
#pragma unroll
    for (int rr = 0; rr < 2; rr++) {
        int ri = rs + rr * 16;                    // local out-row (N dim)
        float v0 = t[2 * u][ri];
        float v1 = t[2 * u + 1][ri];
        size_t o = (size_t)(bx + ri) * Krows + by + 2 * u;
        uint32_t l, h = pack_split(v0, v1, &l);
        *(uint32_t*)(hi + o) = h;
        *(uint32_t*)(lo + o) = l;
    }
}

// ---------------- launch 1: ALL prep ----------------
__global__ void prep_kernel(const float* __restrict__ x,
                            const float* __restrict__ Wq,
                            const float* __restrict__ Wk,
                            const float* __restrict__ Wv,
                            const float* __restrict__ Wo) {
    int b = blockIdx.x;
    int tid = threadIdx.x;
    if (b < PREP_ROPE_BLOCKS) {
        int idx = b * 256 + tid;
        int s = idx >> 5, d2 = idx & 31;
        double inv = exp(-(double)d2 * 0.28782313662425572);
        double f = (double)s * inv;
        g_cos[idx] = (float)cos(f);
        g_sin[idx] = (float)sin(f);
        return;
    }
    if (b < PREP_ROPE_BLOCKS + PREP_X_BLOCKS) {
        int i4 = ((b - PREP_ROPE_BLOCKS) * 256 + tid) * 4;
        float4 v = *(const float4*)(x + i4);
        uint32_t l0, h0 = pack_split(v.x, v.y, &l0);
        uint32_t l1, h1 = pack_split(v.z, v.w, &l1);
        *(uint32_t*)(g_xhi + i4)     = h0;
        *(uint32_t*)(g_xhi + i4 + 2) = h1;
        *(uint32_t*)(g_xlo + i4)     = l0;
        *(uint32_t*)(g_xlo + i4 + 2) = l1;
        return;
    }
    if (b < PREP_ROPE_BLOCKS + PREP_X_BLOCKS + PREP_QKV_BLOCKS) {
        int i = b - PREP_ROPE_BLOCKS - PREP_X_BLOCKS;
        int bx = i % 96, by = i / 96;
        if (bx < 64)      conv_wt_body(Wq, g_wqh, g_wql, DMODEL, QDIM,  bx,      by, tid);
        else if (bx < 80) conv_wt_body(Wk, g_wkh, g_wkl, DMODEL, KVDIM, bx - 64, by, tid);
        else              conv_wt_body(Wv, g_wvh, g_wvl, DMODEL, KVDIM, bx - 80, by, tid);
    } else {
        int i = b - PREP_ROPE_BLOCKS - PREP_X_BLOCKS - PREP_QKV_BLOCKS;
        conv_wt_body(Wo, g_woh, g_wol, QDIM, DMODEL, i % 64, i / 64, tid);
    }
}

// ---------------- mma.sync GEMM core (2-stage, templated on M-tile) ----------------
template<int MT>
__device__ __forceinline__ void gemm_core(
    const __nv_bfloat16* __restrict__ Ahi, const __nv_bfloat16* __restrict__ Alo,
    const __nv_bfloat16* __restrict__ Bhi, const __nv_bfloat16* __restrict__ Blo,
    int K, int m0, int n0, char* smem,
    int mode, float* __restrict__ C, int ldc,
    __nv_bfloat16* __restrict__ dhi, __nv_bfloat16* __restrict__ dlo)
{
    constexpr int A_TILE = MT * 64 * 80;
    constexpr int OFF_AL = A_TILE;
    constexpr int OFF_BH = 2 * A_TILE;
    constexpr int STAGE  = 2 * A_TILE + 2 * B_TILE_B;
    constexpr int RSTRIDE = MT * 32;
    constexpr int BREPS = 4 / MT;

    int tid = threadIdx.x, lane = tid & 31, wid = tid >> 5;
    int wm = wid >> 2, wn = wid & 3;
    uint32_t sb = smem_u32(smem);

    const __nv_bfloat16* srcA[2] = { Ahi + (size_t)m0 * K, Alo + (size_t)m0 * K };
    const __nv_bfloat16* srcB[2] = { Bhi + (size_t)n0 * K, Blo + (size_t)n0 * K };

    float acc[4][4][4];
#pragma unroll
    for (int a = 0; a < 4; a++)
#pragma unroll
        for (int b = 0; b < 4; b++)
#pragma unroll
            for (int c = 0; c < 4; c++) acc[a][b][c] = 0.f;

    const int nchunks = K / KC;
    int row0 = tid >> 2, seg = tid & 3;

    {
        uint32_t st = sb;
#pragma unroll
        for (int comp = 0; comp < 2; comp++) {
#pragma unroll
            for (int it = 0; it < 2; it++) {
                int r = row0 + it * RSTRIDE;
                cp16(st + comp * A_TILE + r * 80 + seg * 16,
                     srcA[comp] + (size_t)r * K + seg * 8);
            }
#pragma unroll
            for (int ib = 0; ib < BREPS; ib++) {
                int r = row0 + ib * RSTRIDE;
                cp16(st + OFF_BH + comp * B_TILE_B + r * 80 + seg * 16,
                     srcB[comp] + (size_t)r * K + seg * 8);
            }
        }
        asm volatile("cp.async.commit_group;");
    }

    for (int i = 0; i < nchunks; i++) {
        asm volatile("cp.async.wait_group 0;");
        __syncthreads();

        if (i + 1 < nchunks) {
            uint32_t st = sb + ((i + 1) & 1) * STAGE;
            int k0 = (i + 1) * KC;
#pragma unroll
            for (int comp = 0; comp < 2; comp++) {
#pragma unroll
                for (int it = 0; it < 2; it++) {
                    int r = row0 + it * RSTRIDE;
                    cp16(st + comp * A_TILE + r * 80 + seg * 16,
                         srcA[comp] + (size_t)r * K + k0 + seg * 8);
                }
#pragma unroll
                for (int ib = 0; ib < BREPS; ib++) {
                    int r = row0 + ib * RSTRIDE;
                    cp16(st + OFF_BH + comp * B_TILE_B + r * 80 + seg * 16,
                         srcB[comp] + (size_t)r * K + k0 + seg * 8);
                }
            }
            asm volatile("cp.async.commit_group;");
        }

        uint32_t st = sb + (i & 1) * STAGE;
#pragma unroll
        for (int ks = 0; ks < 2; ks++) {
            uint32_t bh[4][2], bl[4][2];
            uint32_t brow = wn * 32 + ((lane >> 4) & 1) * 8 + (lane & 7);
            uint32_t bcol = ks * 16 + ((lane >> 3) & 1) * 8;
#pragma unroll
            for (int pr = 0; pr < 2; pr++) {
                uint32_t bd = st + OFF_BH + (brow + pr * 16) * 80 + bcol * 2;
                uint32_t t4[4];
                ldsm4(t4, bd);
                bh[2 * pr][0] = t4[0]; bh[2 * pr][1] = t4[1];
                bh[2 * pr + 1][0] = t4[2]; bh[2 * pr + 1][1] = t4[3];
                ldsm4(t4, bd + B_TILE_B);
                bl[2 * pr][0] = t4[0]; bl[2 * pr][1] = t4[1];
                bl[2 * pr + 1][0] = t4[2]; bl[2 * pr + 1][1] = t4[3];
            }
            uint32_t arow = wm * 64 + (lane & 15);
            uint32_t acol = ks * 16 + (lane >> 4) * 8;
#pragma unroll
            for (int mi = 0; mi < 4; mi++) {
                uint32_t ah[4], al[4];
                uint32_t ad = st + (arow + mi * 16) * 80 + acol * 2;
                ldsm4(ah, ad);
                ldsm4(al, ad + OFF_AL);
#pragma unroll
                for (int ni = 0; ni < 4; ni++) {
                    mma_bf16(acc[mi][ni], ah, bh[ni]);
                    mma_bf16(acc[mi][ni], ah, bl[ni]);
                    mma_bf16(acc[mi][ni], al, bh[ni]);
                }
            }
        }
    }

    int r4 = lane >> 2, c2 = (lane & 3) * 2;
    if (mode == 0) {
        float* Cw = C + (size_t)(m0 + wm * 64) * ldc + n0 + wn * 32;
#pragma unroll
        for (int mi = 0; mi < 4; mi++)
#pragma unroll
            for (int ni = 0; ni < 4; ni++) {
                float* p = Cw + (size_t)(mi * 16 + r4) * ldc + ni * 8 + c2;
                *(float2*)p = make_float2(acc[mi][ni][0], acc[mi][ni][1]);
                *(float2*)(p + (size_t)8 * ldc) = make_float2(acc[mi][ni][2], acc[mi][ni][3]);
            }
    } else {
        float qsc = (mode == 1) ? 0.18033688011112042f : 1.0f;
#pragma unroll
        for (int mi = 0; mi < 4; mi++)
#pragma unroll
            for (int ni = 0; ni < 4; ni++) {
                int col = n0 + wn * 32 + ni * 8 + c2;
                int h = col >> 6, d2 = (col & 63) >> 1;
#pragma unroll
                for (int half = 0; half < 2; half++) {
                    int s = m0 + wm * 64 + mi * 16 + r4 + half * 8;
                    float v0 = acc[mi][ni][half * 2];
                    float v1 = acc[mi][ni][half * 2 + 1];
                    float o0, o1;
                    if (mode == 3) { o0 = v0; o1 = v1; }
                    else {
                        float c = g_cos[s * 32 + d2], sn = g_sin[s * 32 + d2];
                        o0 = (v0 * c - v1 * sn) * qsc;
                        o1 = (v0 * sn + v1 * c) * qsc;
                    }
                    size_t off = ((size_t)h * SEQ + s) * HD + 2 * d2;
                    uint32_t lo, hi = pack_split(o0, o1, &lo);
                    *(uint32_t*)(dhi + off) = hi;
                    *(uint32_t*)(dlo + off) = lo;
                }
            }
    }
}

// launch 2: fused QKV GEMM + RoPE (128x128, 256 thr, 2 CTA/SM)
__global__ void __launch_bounds__(256, 2) qkv_gemm_kernel() {
    extern __shared__ char smem[];
    int bn = blockIdx.x, bm = blockIdx.y;
    if (bn < 16)
        gemm_core<2>(g_xhi, g_xlo, g_wqh, g_wql, DMODEL, bm * 128, bn * 128, smem,
                     1, nullptr, 0, g_qh, g_ql);
    else if (bn < 20)
        gemm_core<2>(g_xhi, g_xlo, g_wkh, g_wkl, DMODEL, bm * 128, (bn - 16) * 128, smem,
                     2, nullptr, 0, g_kh, g_kl);
    else
        gemm_core<2>(g_xhi, g_xlo, g_wvh, g_wvl, DMODEL, bm * 128, (bn - 20) * 128, smem,
                     3, nullptr, 0, g_vh, g_vl);
}

// launch 4: output projection (256x128, 512 thr, 128 CTAs = one balanced wave)
__global__ void __launch_bounds__(512, 1) out_gemm_kernel(float* __restrict__ out) {
    extern __shared__ char smem[];
    gemm_core<4>(g_ahi, g_alo, g_woh, g_wol, QDIM,
                 blockIdx.y * 256, blockIdx.x * 128, smem,
                 0, out, DMODEL, nullptr, nullptr);
}

// ---------------- launch 3: tensor-core flash attention ----------------
__global__ __launch_bounds__(128) void attn_mma_kernel() {
    extern __shared__ char smc[];
    uint32_t sb = smem_u32(smc);
    int tid = threadIdx.x, lane = tid & 31, w = tid >> 5;
    int qb = (int)gridDim.x - 1 - (int)blockIdx.x;
    int h = blockIdx.y, kvh = h >> 2;

    const __nv_bfloat16* qh_g = g_qh + ((size_t)h * SEQ + qb * 64) * HD;
    const __nv_bfloat16* ql_g = g_ql + ((size_t)h * SEQ + qb * 64) * HD;
    const __nv_bfloat16* kv_g[4] = {
        g_kh + (size_t)kvh * SEQ * HD, g_kl + (size_t)kvh * SEQ * HD,
        g_vh + (size_t)kvh * SEQ * HD, g_vl + (size_t)kvh * SEQ * HD };

#pragma unroll
    for (int i = 0; i < 8; i++) {
        int c = tid + i * 128;
        int comp = c >> 9, idx = c & 511, row = idx >> 3, seg = idx & 7;
        const __nv_bfloat16* s = (comp ? ql_g : qh_g) + row * HD + seg * 8;
        cp16(sb + comp * ATT_COMP + row * ATT_STRIDE + seg * 16, s);
    }
    {
        uint32_t base = sb + ATT_STAGE;
#pragma unroll
        for (int i = 0; i < 16; i++) {
            int c = tid + i * 128;
            int comp = c >> 9, idx = c & 511, row = idx >> 3, seg = idx & 7;
            cp16(base + comp * ATT_COMP + row * ATT_STRIDE + seg * 16,
                 kv_g[comp] + (size_t)row * HD + seg * 8);
        }
    }
    asm volatile("cp.async.commit_group;");

    float m0 = -1e30f, m1 = -1e30f, l0 = 0.f, l1 = 0.f;
    float oacc[8][4];
#pragma unroll
    for (int j = 0; j < 8; j++)
#pragma unroll
        for (int e = 0; e < 4; e++) oacc[j][e] = 0.f;

    uint32_t qfh[4][4], qfl[4][4];

    for (int kb = 0; kb <= qb; kb++) {
        asm volatile("cp.async.wait_group 0;");
        __syncthreads();

        if (kb == 0) {
#pragma unroll
            for (int ks = 0; ks < 4; ks++) {
                uint32_t ad = sb + (w * 16 + (lane & 15)) * ATT_STRIDE
                            + (ks * 16 + ((lane >> 4) << 3)) * 2;
                ldsm4(qfh[ks], ad);
                ldsm4(qfl[ks], ad + ATT_COMP);
            }
            __syncthreads();
        }

        if (kb < qb) {
            uint32_t base = sb + (kb & 1) * ATT_STAGE;
#pragma unroll
            for (int i = 0; i < 16; i++) {
                int c = tid + i * 128;
                int comp = c >> 9, idx = c & 511, row = idx >> 3, seg = idx & 7;
                cp16(base + comp * ATT_COMP + row * ATT_STRIDE + seg * 16,
                     kv_g[comp] + (size_t)((kb + 1) * 64 + row) * HD + seg * 8);
            }
            asm volatile("cp.async.commit_group;");
        }

        uint32_t stg = sb + ((kb + 1) & 1) * ATT_STAGE;

        float sacc[8][4];
#pragma unroll
        for (int j = 0; j < 8; j++)
#pragma unroll
            for (int e = 0; e < 4; e++) sacc[j][e] = 0.f;

#pragma unroll
        for (int ks = 0; ks < 4; ks++) {
#pragma unroll
            for (int jp = 0; jp < 4; jp++) {
                uint32_t r = jp * 16 + ((lane >> 3) & 1) * 8 + (lane & 7);
                uint32_t ad = stg + r * ATT_STRIDE + (ks * 16 + (lane >> 4) * 8) * 2;
                uint32_t bh[4], bl[4];
                ldsm4(bh, ad);
                ldsm4(bl, ad + ATT_COMP);
                uint32_t b0h[2] = {bh[0], bh[2]}, b1h[2] = {bh[1], bh[3]};
                uint32_t b0l[2] = {bl[0], bl[2]}, b1l[2] = {bl[1], bl[3]};
                mma_bf16(sacc[2 * jp],     qfh[ks], b0h);
                mma_bf16(sacc[2 * jp],     qfh[ks], b0l);
                mma_bf16(sacc[2 * jp],     qfl[ks], b0h);
                mma_bf16(sacc[2 * jp + 1], qfh[ks], b1h);
                mma_bf16(sacc[2 * jp + 1], qfh[ks], b1l);
                mma_bf16(sacc[2 * jp + 1], qfl[ks], b1h);
            }
        }

        if (kb == qb) {
            int rb = w * 16 + (lane >> 2), cb = (lane & 3) * 2;
#pragma unroll
            for (int j = 0; j < 8; j++)
#pragma unroll
                for (int e = 0; e < 4; e++) {
                    int col = j * 8 + cb + (e & 1);
                    int rowi = rb + ((e & 2) ? 8 : 0);
                    if (col > rowi) sacc[j][e] = -1e30f;
                }
        }

        float mx0 = -1e30f, mx1 = -1e30f;
#pragma unroll
        for (int j = 0; j < 8; j++) {
            mx0 = fmaxf(mx0, fmaxf(sacc[j][0], sacc[j][1]));
            mx1 = fmaxf(mx1, fmaxf(sacc[j][2], sacc[j][3]));
        }
        mx0 = fmaxf(mx0, __shfl_xor_sync(0xffffffffu, mx0, 1));
        mx0 = fmaxf(mx0, __shfl_xor_sync(0xffffffffu, mx0, 2));
        mx1 = fmaxf(mx1, __shfl_xor_sync(0xffffffffu, mx1, 1));
        mx1 = fmaxf(mx1, __shfl_xor_sync(0xffffffffu, mx1, 2));
        float nm0 = fmaxf(m0, mx0), nm1 = fmaxf(m1, mx1);

        bool noup = __all_sync(0xffffffffu, (nm0 == m0) && (nm1 == m1));
        if (!noup) {
            float cr0 = exp2f(m0 - nm0), cr1 = exp2f(m1 - nm1);
            l0 *= cr0; l1 *= cr1;
#pragma unroll
            for (int j = 0; j < 8; j++) {
                oacc[j][0] *= cr0; oacc[j][1] *= cr0;
                oacc[j][2] *= cr1; oacc[j][3] *= cr1;
            }
            m0 = nm0; m1 = nm1;
        }

        uint32_t pah[4][4], pal[4][4];
#pragma unroll
        for (int ks = 0; ks < 4; ks++) {
            int j0 = 2 * ks, j1 = 2 * ks + 1;
            float p00 = exp2f(sacc[j0][0] - m0), p01 = exp2f(sacc[j0][1] - m0);
            float p02 = exp2f(sacc[j0][2] - m1), p03 = exp2f(sacc[j0][3] - m1);
            float p10 = exp2f(sacc[j1][0] - m0), p11 = exp2f(sacc[j1][1] - m0);
            float p12 = exp2f(sacc[j1][2] - m1), p13 = exp2f(sacc[j1][3] - m1);
            l0 += (p00 + p01) + (p10 + p11);
            l1 += (p02 + p03) + (p12 + p13);
            pah[ks][0] = pack_split(p00, p01, &pal[ks][0]);
            pah[ks][1] = pack_split(p02, p03, &pal[ks][1]);
            pah[ks][2] = pack_split(p10, p11, &pal[ks][2]);
            pah[ks][3] = pack_split(p12, p13, &pal[ks][3]);
        }

#pragma unroll
        for (int ks = 0; ks < 4; ks++) {
#pragma unroll
            for (int jp = 0; jp < 4; jp++) {
                uint32_t r = ks * 16 + ((lane >> 4) << 3) + (lane & 7);
                uint32_t ad = stg + 2 * ATT_COMP + r * ATT_STRIDE
                            + (jp * 16 + ((lane >> 3) & 1) * 8) * 2;
                uint32_t vh[4], vl[4];
                ldsm4t(vh, ad);
                ldsm4t(vl, ad + ATT_COMP);
                uint32_t v0h[2] = {vh[0], vh[2]}, v1h[2] = {vh[1], vh[3]};
                uint32_t v0l[2] = {vl[0], vl[2]}, v1l[2] = {vl[1], vl[3]};
                mma_bf16(oacc[2 * jp],     pah[ks], v0h);
                mma_bf16(oacc[2 * jp],     pah[ks], v0l);
                mma_bf16(oacc[2 * jp],     pal[ks], v0h);
                mma_bf16(oacc[2 * jp + 1], pah[ks], v1h);
                mma_bf16(oacc[2 * jp + 1], pah[ks], v1l);
                mma_bf16(oacc[2 * jp + 1], pal[ks], v1h);
            }
        }
    }

    l0 += __shfl_xor_sync(0xffffffffu, l0, 1);
    l0 += __shfl_xor_sync(0xffffffffu, l0, 2);
    l1 += __shfl_xor_sync(0xffffffffu, l1, 1);
    l1 += __shfl_xor_sync(0xffffffffu, l1, 2);

    float i0 = 1.f / l0, i1 = 1.f / l1;
    int r0 = qb * 64 + w * 16 + (lane >> 2);
    size_t colb = (size_t)h * HD + (lane & 3) * 2;
#pragma unroll
    for (int j = 0; j < 8; j++) {
        size_t o0 = (size_t)r0 * QDIM + colb + j * 8;
        size_t o1 = (size_t)(r0 + 8) * QDIM + colb + j * 8;
        uint32_t lo0, hi0 = pack_split(oacc[j][0] * i0, oacc[j][1] * i0, &lo0);
        uint32_t lo1, hi1 = pack_split(oacc[j][2] * i1, oacc[j][3] * i1, &lo1);
        *(uint32_t*)(g_ahi + o0) = hi0;
        *(uint32_t*)(g_alo + o0) = lo0;
        *(uint32_t*)(g_ahi + o1) = hi1;
        *(uint32_t*)(g_alo + o1) = lo1;
    }
}

// ---------------------------------------------------------------------------
extern "C" void kernel_launch(void* const* d_in, const int* in_sizes, int n_in,
                              void* d_out, int out_size) {
    const float* x  = (const float*)d_in[0];
    const float* Wq = (const float*)d_in[1];
    const float* Wk = (const float*)d_in[2];
    const float* Wv = (const float*)d_in[3];
    const float* Wo = (const float*)d_in[4];
    float* out = (float*)d_out;

    cudaFuncSetAttribute(qkv_gemm_kernel,
                         cudaFuncAttributeMaxDynamicSharedMemorySize, GEMM_SMEM_MT2);
    cudaFuncSetAttribute(out_gemm_kernel,
                         cudaFuncAttributeMaxDynamicSharedMemorySize, GEMM_SMEM_MT4);
    cudaFuncSetAttribute(attn_mma_kernel,
                         cudaFuncAttributeMaxDynamicSharedMemorySize, ATT_SMEM);

    prep_kernel<<<PREP_BLOCKS, 256>>>(x, Wq, Wk, Wv, Wo);
    qkv_gemm_kernel<<<dim3(24, 16), 256, GEMM_SMEM_MT2>>>();
    attn_mma_kernel<<<dim3(SEQ / 64, NH), 128, ATT_SMEM>>>();
    out_gemm_kernel<<<dim3(16, 8), 512, GEMM_SMEM_MT4>>>(out);
}